// round 10
// baseline (speedup 1.0000x reference)
#include <cuda_runtime.h>

#define NB 2
#define NT 2048
#define NE 1024
#define NH 16
#define ND 64
#define NK 1024

// Scratch (no allocation allowed in kernel_launch)
__device__ float g_q[NB*NH*NT*ND];
__device__ float g_k[NB*NH*NT*ND];
__device__ float g_v[NB*NH*NT*ND];
__device__ float g_o[(size_t)NB*NT*NE];

// ---------------------------------------------------------------------------
// GEMM 1: C[4096,3072] = X[4096,1024] @ W^T (W[3072,1024]) + bias
// Epilogue scatters into g_q/g_k/g_v laid out [B,H,T,D].
// 128x128x16 tile, 256 threads, 8x8 per-thread, stride-16 fragment mapping.
// ---------------------------------------------------------------------------
__global__ __launch_bounds__(256) void qkv_gemm_kernel(const float* __restrict__ X,
                                                       const float* __restrict__ W,
                                                       const float* __restrict__ bias) {
    __shared__ float As[16][128];
    __shared__ float Bs[16][128];
    const int tid = threadIdx.x;
    const int tx = tid & 15, ty = tid >> 4;
    const int row0 = blockIdx.y * 128;
    const int col0 = blockIdx.x * 128;

    float acc[8][8];
#pragma unroll
    for (int i = 0; i < 8; i++)
#pragma unroll
        for (int j = 0; j < 8; j++) acc[i][j] = 0.f;

    const int lr = tid >> 2;          // 0..63
    const int lk = (tid & 3) << 2;    // 0,4,8,12
    const float* xp = X + (size_t)(row0 + lr) * NK + lk;
    const float* wp = W + (size_t)(col0 + lr) * NK + lk;

    for (int k0 = 0; k0 < NK; k0 += 16) {
        float4 a0 = *(const float4*)(xp + k0);
        float4 a1 = *(const float4*)(xp + (size_t)64 * NK + k0);
        float4 b0 = *(const float4*)(wp + k0);
        float4 b1 = *(const float4*)(wp + (size_t)64 * NK + k0);
        As[lk+0][lr]    = a0.x; As[lk+1][lr]    = a0.y; As[lk+2][lr]    = a0.z; As[lk+3][lr]    = a0.w;
        As[lk+0][lr+64] = a1.x; As[lk+1][lr+64] = a1.y; As[lk+2][lr+64] = a1.z; As[lk+3][lr+64] = a1.w;
        Bs[lk+0][lr]    = b0.x; Bs[lk+1][lr]    = b0.y; Bs[lk+2][lr]    = b0.z; Bs[lk+3][lr]    = b0.w;
        Bs[lk+0][lr+64] = b1.x; Bs[lk+1][lr+64] = b1.y; Bs[lk+2][lr+64] = b1.z; Bs[lk+3][lr+64] = b1.w;
        __syncthreads();
#pragma unroll
        for (int kk = 0; kk < 16; kk++) {
            float af[8], bf[8];
#pragma unroll
            for (int i = 0; i < 8; i++) af[i] = As[kk][ty + 16*i];
#pragma unroll
            for (int j = 0; j < 8; j++) bf[j] = Bs[kk][tx + 16*j];
#pragma unroll
            for (int i = 0; i < 8; i++)
#pragma unroll
                for (int j = 0; j < 8; j++)
                    acc[i][j] = fmaf(af[i], bf[j], acc[i][j]);
        }
        __syncthreads();
    }

    // col0 is 128-aligned and 1024 % 128 == 0 -> 'which' is uniform per block
    const int which = col0 >> 10;
    float* dstbase = (which == 0) ? g_q : (which == 1 ? g_k : g_v);
#pragma unroll
    for (int j = 0; j < 8; j++) {
        const int col = col0 + tx + 16*j;
        const int e = col & (NE - 1);
        const int h = e >> 6;
        const int d = e & 63;
        const float bj = bias[col];
#pragma unroll
        for (int i = 0; i < 8; i++) {
            const int row = row0 + ty + 16*i;
            const int b = row >> 11;
            const int t = row & (NT - 1);
            dstbase[(((size_t)(b * NH + h)) * NT + t) * ND + d] = acc[i][j] + bj;
        }
    }
}

// ---------------------------------------------------------------------------
// Flash attention: one block = one (b,h) x 64-query tile. 256 threads.
// Qs/KP swizzled by (row & 31) for conflict-free strided reads.
// KP buffer is reused: K tile during S = Q K^T, then P = exp(S - m) for PV.
// ---------------------------------------------------------------------------
__global__ __launch_bounds__(256) void attn_kernel() {
    __shared__ float Qs[64][64];  // Qs[i][d ^ (i&31)]
    __shared__ float KP[64][64];  // K: KP[j][d ^ (j&31)]; then P: KP[i][k ^ (i&31)]
    __shared__ float Vs[64][64];  // Vs[k][d] plain

    const int tid = threadIdx.x;
    const int tx = tid & 15, ty = tid >> 4;
    const int bh = blockIdx.y;
    const int q0 = blockIdx.x * 64;

    const float* Qg = g_q + (size_t)bh * NT * ND;
    const float* Kg = g_k + (size_t)bh * NT * ND;
    const float* Vg = g_v + (size_t)bh * NT * ND;

    // Load Q tile (swizzled)
    for (int it = tid; it < 64 * 16; it += 256) {
        const int r = it >> 4;
        const int c = (it & 15) << 2;
        float4 v = *(const float4*)(Qg + (size_t)(q0 + r) * ND + c);
        const int s = r & 31;
        Qs[r][(c + 0) ^ s] = v.x; Qs[r][(c + 1) ^ s] = v.y;
        Qs[r][(c + 2) ^ s] = v.z; Qs[r][(c + 3) ^ s] = v.w;
    }

    float mrow[4], lrow[4], acc[4][4];
#pragma unroll
    for (int i = 0; i < 4; i++) {
        mrow[i] = -3.0e38f; lrow[i] = 0.f;
#pragma unroll
        for (int j = 0; j < 4; j++) acc[i][j] = 0.f;
    }
    __syncthreads();

    for (int k0 = 0; k0 < NT; k0 += 64) {
        // Load K (swizzled) and V (plain) tiles
        for (int it = tid; it < 64 * 16; it += 256) {
            const int r = it >> 4;
            const int c = (it & 15) << 2;
            float4 kv = *(const float4*)(Kg + (size_t)(k0 + r) * ND + c);
            const int s = r & 31;
            KP[r][(c + 0) ^ s] = kv.x; KP[r][(c + 1) ^ s] = kv.y;
            KP[r][(c + 2) ^ s] = kv.z; KP[r][(c + 3) ^ s] = kv.w;
            float4 vv = *(const float4*)(Vg + (size_t)(k0 + r) * ND + c);
            *(float4*)&Vs[r][c] = vv;
        }
        __syncthreads();

        // S = Q K^T : thread owns rows 4ty..4ty+3, cols tx+16j
        float sv[4][4];
#pragma unroll
        for (int i = 0; i < 4; i++)
#pragma unroll
            for (int j = 0; j < 4; j++) sv[i][j] = 0.f;

        for (int d = 0; d < 64; d++) {
            float qf[4], kf[4];
#pragma unroll
            for (int i = 0; i < 4; i++) {
                const int r = 4 * ty + i;
                qf[i] = Qs[r][d ^ (r & 31)];
            }
#pragma unroll
            for (int j = 0; j < 4; j++) {
                const int r = tx + 16 * j;
                kf[j] = KP[r][d ^ (r & 31)];
            }
#pragma unroll
            for (int i = 0; i < 4; i++)
#pragma unroll
                for (int j = 0; j < 4; j++)
                    sv[i][j] = fmaf(qf[i], kf[j], sv[i][j]);
        }

        // Online softmax (row reduction across the 16 tx lanes of a half-warp)
#pragma unroll
        for (int i = 0; i < 4; i++) {
            float mx = -3.0e38f;
#pragma unroll
            for (int j = 0; j < 4; j++) {
                sv[i][j] *= 0.125f;   // 1/sqrt(64)
                mx = fmaxf(mx, sv[i][j]);
            }
#pragma unroll
            for (int off = 8; off >= 1; off >>= 1)
                mx = fmaxf(mx, __shfl_xor_sync(0xffffffffu, mx, off));
            const float mnew = fmaxf(mrow[i], mx);
            const float corr = __expf(mrow[i] - mnew);
            float rs = 0.f;
#pragma unroll
            for (int j = 0; j < 4; j++) {
                sv[i][j] = __expf(sv[i][j] - mnew);
                rs += sv[i][j];
            }
#pragma unroll
            for (int off = 8; off >= 1; off >>= 1)
                rs += __shfl_xor_sync(0xffffffffu, rs, off);
            lrow[i] = lrow[i] * corr + rs;
            mrow[i] = mnew;
#pragma unroll
            for (int j = 0; j < 4; j++) acc[i][j] *= corr;
        }
        __syncthreads();   // everyone done reading K from KP

        // Write P into KP (row-swizzled)
#pragma unroll
        for (int i = 0; i < 4; i++) {
            const int r = 4 * ty + i;
            const int s = r & 31;
#pragma unroll
            for (int j = 0; j < 4; j++)
                KP[r][(tx + 16 * j) ^ s] = sv[i][j];
        }
        __syncthreads();

        // O += P @ V : thread owns O rows 4ty..4ty+3, d cols tx+16j
        for (int k = 0; k < 64; k++) {
            float pf[4], vf[4];
#pragma unroll
            for (int i = 0; i < 4; i++) {
                const int r = 4 * ty + i;
                pf[i] = KP[r][k ^ (r & 31)];
            }
#pragma unroll
            for (int j = 0; j < 4; j++)
                vf[j] = Vs[k][tx + 16 * j];
#pragma unroll
            for (int i = 0; i < 4; i++)
#pragma unroll
                for (int j = 0; j < 4; j++)
                    acc[i][j] = fmaf(pf[i], vf[j], acc[i][j]);
        }
        __syncthreads();   // before next tile overwrites KP/Vs
    }

    // Epilogue: write [B,T,E] so the output projection is a plain GEMM
    const int b = bh >> 4;
    const int h = bh & 15;
#pragma unroll
    for (int i = 0; i < 4; i++) {
        const float inv = 1.f / lrow[i];
        const int t = q0 + 4 * ty + i;
#pragma unroll
        for (int j = 0; j < 4; j++) {
            const int d = tx + 16 * j;
            g_o[((size_t)(b * NT + t)) * NE + h * ND + d] = acc[i][j] * inv;
        }
    }
}

// ---------------------------------------------------------------------------
// GEMM 2: out[4096,1024] = g_o @ out_w^T + out_b
// ---------------------------------------------------------------------------
__global__ __launch_bounds__(256) void out_gemm_kernel(const float* __restrict__ W,
                                                       const float* __restrict__ bias,
                                                       float* __restrict__ out) {
    __shared__ float As[16][128];
    __shared__ float Bs[16][128];
    const int tid = threadIdx.x;
    const int tx = tid & 15, ty = tid >> 4;
    const int row0 = blockIdx.y * 128;
    const int col0 = blockIdx.x * 128;

    float acc[8][8];
#pragma unroll
    for (int i = 0; i < 8; i++)
#pragma unroll
        for (int j = 0; j < 8; j++) acc[i][j] = 0.f;

    const int lr = tid >> 2;
    const int lk = (tid & 3) << 2;
    const float* xp = g_o + (size_t)(row0 + lr) * NK + lk;
    const float* wp = W + (size_t)(col0 + lr) * NK + lk;

    for (int k0 = 0; k0 < NK; k0 += 16) {
        float4 a0 = *(const float4*)(xp + k0);
        float4 a1 = *(const float4*)(xp + (size_t)64 * NK + k0);
        float4 b0 = *(const float4*)(wp + k0);
        float4 b1 = *(const float4*)(wp + (size_t)64 * NK + k0);
        As[lk+0][lr]    = a0.x; As[lk+1][lr]    = a0.y; As[lk+2][lr]    = a0.z; As[lk+3][lr]    = a0.w;
        As[lk+0][lr+64] = a1.x; As[lk+1][lr+64] = a1.y; As[lk+2][lr+64] = a1.z; As[lk+3][lr+64] = a1.w;
        Bs[lk+0][lr]    = b0.x; Bs[lk+1][lr]    = b0.y; Bs[lk+2][lr]    = b0.z; Bs[lk+3][lr]    = b0.w;
        Bs[lk+0][lr+64] = b1.x; Bs[lk+1][lr+64] = b1.y; Bs[lk+2][lr+64] = b1.z; Bs[lk+3][lr+64] = b1.w;
        __syncthreads();
#pragma unroll
        for (int kk = 0; kk < 16; kk++) {
            float af[8], bf[8];
#pragma unroll
            for (int i = 0; i < 8; i++) af[i] = As[kk][ty + 16*i];
#pragma unroll
            for (int j = 0; j < 8; j++) bf[j] = Bs[kk][tx + 16*j];
#pragma unroll
            for (int i = 0; i < 8; i++)
#pragma unroll
                for (int j = 0; j < 8; j++)
                    acc[i][j] = fmaf(af[i], bf[j], acc[i][j]);
        }
        __syncthreads();
    }

#pragma unroll
    for (int j = 0; j < 8; j++) {
        const int col = col0 + tx + 16*j;
        const float bj = bias[col];
#pragma unroll
        for (int i = 0; i < 8; i++) {
            const int row = row0 + ty + 16*i;
            out[(size_t)row * NE + col] = acc[i][j] + bj;
        }
    }
}

// ---------------------------------------------------------------------------
extern "C" void kernel_launch(void* const* d_in, const int* in_sizes, int n_in,
                              void* d_out, int out_size) {
    const float* x     = (const float*)d_in[0];  // [2,2048,1024]
    const float* qkv_w = (const float*)d_in[1];  // [3072,1024]
    const float* qkv_b = (const float*)d_in[2];  // [3072]
    const float* out_w = (const float*)d_in[3];  // [1024,1024]
    const float* out_b = (const float*)d_in[4];  // [1024]
    float* out = (float*)d_out;                  // [2,2048,1024]

    dim3 g1(3 * NE / 128, NB * NT / 128);   // (24, 32)
    qkv_gemm_kernel<<<g1, 256>>>(x, qkv_w, qkv_b);

    dim3 ga(NT / 64, NB * NH);              // (32, 32)
    attn_kernel<<<ga, 256>>>();

    dim3 g2(NE / 128, NB * NT / 128);       // (8, 32)
    out_gemm_kernel<<<g2, 256>>>(out_w, out_b, out);
}

// round 17
// speedup vs baseline: 1.8934x; 1.8934x over previous
#include <cuda_runtime.h>

#define NB 2
#define NT 2048
#define NE 1024
#define NH 16
#define ND 64
#define NK 1024

// Scratch (no allocation allowed in kernel_launch)
__device__ float g_q[NB*NH*NT*ND];
__device__ float g_k[NB*NH*NT*ND];
__device__ float g_v[NB*NH*NT*ND];
__device__ float g_o[(size_t)NB*NT*NE];

// ---------------------------------------------------------------------------
// tf32 helpers
// ---------------------------------------------------------------------------
__device__ __forceinline__ unsigned f2tf(float x) {
    unsigned r;
    asm("cvt.rna.tf32.f32 %0, %1;" : "=r"(r) : "f"(x));
    return r;
}
__device__ __forceinline__ float f2tff(float x) { return __uint_as_float(f2tf(x)); }

// D += A*B, m16n8k8 tf32. a0:[g][tg] a1:[g+8][tg] a2:[g][tg+4] a3:[g+8][tg+4]
// b0:[k=tg][n=g] b1:[k=tg+4][n=g]; C: c0:[g][2tg] c1:[g][2tg+1] c2:[g+8][2tg] c3:[g+8][2tg+1]
__device__ __forceinline__ void mma8(float4& d, unsigned a0, unsigned a1, unsigned a2,
                                     unsigned a3, unsigned b0, unsigned b1) {
    asm("mma.sync.aligned.m16n8k8.row.col.f32.tf32.tf32.f32 "
        "{%0,%1,%2,%3}, {%4,%5,%6,%7}, {%8,%9}, {%0,%1,%2,%3};"
        : "+f"(d.x), "+f"(d.y), "+f"(d.z), "+f"(d.w)
        : "r"(a0), "r"(a1), "r"(a2), "r"(a3), "r"(b0), "r"(b1));
}

// ---------------------------------------------------------------------------
// tf32 split GEMM: C[M,N] = X[M,K] @ W[N,K]^T + bias, 3xTF32 (near-fp32).
// Block tile 128x64, BK=16, 8 warps (4x2), warp tile 32x32 (2 m-tiles x 4 n-tiles).
// EPI=0: A = X input, scatter into g_q/g_k/g_v [B,H,T,D].
// EPI=1: A = g_o device global, dense out[row*NE+col].
// ---------------------------------------------------------------------------
template <int EPI>
__global__ __launch_bounds__(256) void gemm_tf32(const float* __restrict__ X,
                                                 const float* __restrict__ W,
                                                 const float* __restrict__ bias,
                                                 float* __restrict__ out) {
    __shared__ float Ah[16][136], Al[16][136];   // stride 136 -> bank = (8k+row)%32
    __shared__ float Bh[16][72],  Bl[16][72];    // stride 72  -> bank = (8k+n)%32

    const float* Xs = (EPI == 1) ? (const float*)g_o : X;   // FIX: never deref nullptr

    const int tid = threadIdx.x;
    const int w = tid >> 5, lane = tid & 31;
    const int g = lane >> 2, tg = lane & 3;
    const int wr = 32 * (w >> 1);   // warp row base within 128
    const int wc = 32 * (w & 1);    // warp col base within 64
    const int row0 = blockIdx.y * 128;
    const int col0 = blockIdx.x * 64;

    float4 acc[2][4];
#pragma unroll
    for (int mi = 0; mi < 2; mi++)
#pragma unroll
        for (int ni = 0; ni < 4; ni++) acc[mi][ni] = make_float4(0.f, 0.f, 0.f, 0.f);

    const int arow = tid >> 1, akq = (tid & 1) * 8;   // A: 128 rows x 16 k
    const int brow = tid >> 2, bkq = (tid & 3) * 4;   // B: 64 rows x 16 k
    const float* xp = Xs + (size_t)(row0 + arow) * NK + akq;
    const float* wp = W + (size_t)(col0 + brow) * NK + bkq;

    float4 ax0 = *(const float4*)(xp);
    float4 ax1 = *(const float4*)(xp + 4);
    float4 bx  = *(const float4*)(wp);

    for (int k0 = 0; k0 < NK; k0 += 16) {
        // split-convert and store to smem
        {
            const float a0v[4] = {ax0.x, ax0.y, ax0.z, ax0.w};
            const float a1v[4] = {ax1.x, ax1.y, ax1.z, ax1.w};
            const float bv[4]  = {bx.x,  bx.y,  bx.z,  bx.w};
#pragma unroll
            for (int j = 0; j < 4; j++) {
                float h0 = f2tff(a0v[j]);
                Ah[akq + j][arow] = h0;
                Al[akq + j][arow] = f2tff(a0v[j] - h0);
                float h1 = f2tff(a1v[j]);
                Ah[akq + 4 + j][arow] = h1;
                Al[akq + 4 + j][arow] = f2tff(a1v[j] - h1);
                float hb = f2tff(bv[j]);
                Bh[bkq + j][brow] = hb;
                Bl[bkq + j][brow] = f2tff(bv[j] - hb);
            }
        }
        __syncthreads();

        if (k0 + 16 < NK) {
            ax0 = *(const float4*)(xp + k0 + 16);
            ax1 = *(const float4*)(xp + k0 + 20);
            bx  = *(const float4*)(wp + k0 + 16);
        }

#pragma unroll
        for (int ks = 0; ks < 2; ks++) {
            const int kb = 8 * ks;
            unsigned ahf[2][4], alf[2][4], bhf[4][2], blf[4][2];
#pragma unroll
            for (int mi = 0; mi < 2; mi++) {
                const int r = wr + 16 * mi + g;
                ahf[mi][0] = __float_as_uint(Ah[kb + tg][r]);
                ahf[mi][1] = __float_as_uint(Ah[kb + tg][r + 8]);
                ahf[mi][2] = __float_as_uint(Ah[kb + tg + 4][r]);
                ahf[mi][3] = __float_as_uint(Ah[kb + tg + 4][r + 8]);
                alf[mi][0] = __float_as_uint(Al[kb + tg][r]);
                alf[mi][1] = __float_as_uint(Al[kb + tg][r + 8]);
                alf[mi][2] = __float_as_uint(Al[kb + tg + 4][r]);
                alf[mi][3] = __float_as_uint(Al[kb + tg + 4][r + 8]);
            }
#pragma unroll
            for (int ni = 0; ni < 4; ni++) {
                const int c = wc + 8 * ni + g;
                bhf[ni][0] = __float_as_uint(Bh[kb + tg][c]);
                bhf[ni][1] = __float_as_uint(Bh[kb + tg + 4][c]);
                blf[ni][0] = __float_as_uint(Bl[kb + tg][c]);
                blf[ni][1] = __float_as_uint(Bl[kb + tg + 4][c]);
            }
#pragma unroll
            for (int mi = 0; mi < 2; mi++)
#pragma unroll
                for (int ni = 0; ni < 4; ni++) {
                    mma8(acc[mi][ni], ahf[mi][0], ahf[mi][1], ahf[mi][2], ahf[mi][3],
                         bhf[ni][0], bhf[ni][1]);
                    mma8(acc[mi][ni], alf[mi][0], alf[mi][1], alf[mi][2], alf[mi][3],
                         bhf[ni][0], bhf[ni][1]);
                    mma8(acc[mi][ni], ahf[mi][0], ahf[mi][1], ahf[mi][2], ahf[mi][3],
                         blf[ni][0], blf[ni][1]);
                }
        }
        __syncthreads();
    }

    // Epilogue
    if (EPI == 0) {
        const int which = col0 >> 10;   // uniform per block (64 | 1024)
        float* dstbase = (which == 0) ? g_q : (which == 1 ? g_k : g_v);
#pragma unroll
        for (int mi = 0; mi < 2; mi++)
#pragma unroll
            for (int ni = 0; ni < 4; ni++) {
                const int c = col0 + wc + 8 * ni + 2 * tg;
                const int e = c & (NE - 1);
                const int hh = e >> 6, dd = e & 63;
                const float b0v = __ldg(bias + c), b1v = __ldg(bias + c + 1);
                const int r0 = row0 + wr + 16 * mi + g;
                {
                    const int bb = r0 >> 11, tt = r0 & (NT - 1);
                    float2 v = make_float2(acc[mi][ni].x + b0v, acc[mi][ni].y + b1v);
                    *(float2*)&dstbase[(((size_t)(bb * NH + hh)) * NT + tt) * ND + dd] = v;
                }
                {
                    const int r1 = r0 + 8;
                    const int bb = r1 >> 11, tt = r1 & (NT - 1);
                    float2 v = make_float2(acc[mi][ni].z + b0v, acc[mi][ni].w + b1v);
                    *(float2*)&dstbase[(((size_t)(bb * NH + hh)) * NT + tt) * ND + dd] = v;
                }
            }
    } else {
#pragma unroll
        for (int mi = 0; mi < 2; mi++)
#pragma unroll
            for (int ni = 0; ni < 4; ni++) {
                const int c = col0 + wc + 8 * ni + 2 * tg;
                const float b0v = __ldg(bias + c), b1v = __ldg(bias + c + 1);
                const int r0 = row0 + wr + 16 * mi + g;
                float2 v0 = make_float2(acc[mi][ni].x + b0v, acc[mi][ni].y + b1v);
                float2 v1 = make_float2(acc[mi][ni].z + b0v, acc[mi][ni].w + b1v);
                *(float2*)&out[(size_t)r0 * NE + c] = v0;
                *(float2*)&out[(size_t)(r0 + 8) * NE + c] = v1;
            }
    }
}

// ---------------------------------------------------------------------------
// tf32 flash attention: block = (b,h) x 64-query tile, 4 warps (128 threads).
// Warp w owns q rows [16w, 16w+16). Q kept entirely in A-fragment registers.
// KP buffer: K tile during S = QK^T, then P = exp(S-m) for PV. Vs: V tile.
// Swizzle: element (r, c) stored at [r][c ^ (r&4)], row stride 72 (pad 8)
// -> all fragment gathers are bank-conflict-free.
// ---------------------------------------------------------------------------
__global__ __launch_bounds__(128) void attn_tf32() {
    __shared__ float KP[64][72];
    __shared__ float Vs[64][72];

    const int tid = threadIdx.x;
    const int w = tid >> 5, lane = tid & 31;
    const int g = lane >> 2, tg = lane & 3;
    const int bh = blockIdx.y;
    const int q0 = blockIdx.x * 64;

    const float* Qg = g_q + (size_t)bh * NT * ND;
    const float* Kg = g_k + (size_t)bh * NT * ND;
    const float* Vg = g_v + (size_t)bh * NT * ND;

    const int lr = tid >> 1, lc0 = (tid & 1) * 32;   // loader mapping: row, col-half
    const int sx = g & 4;                             // fragment-row swizzle bit

    // Stage Q through KP, gather into registers as tf32 A-fragments.
    {
        const float* qp = Qg + (size_t)(q0 + lr) * ND + lc0;
#pragma unroll
        for (int j = 0; j < 8; j++) {
            float4 v = *(const float4*)(qp + 4 * j);
            float4 o = make_float4(f2tff(v.x), f2tff(v.y), f2tff(v.z), f2tff(v.w));
            *(float4*)&KP[lr][(lc0 + 4 * j) ^ (lr & 4)] = o;
        }
    }
    __syncthreads();

    const int qr = 16 * w + g;
    unsigned qa[8][4];
#pragma unroll
    for (int ks = 0; ks < 8; ks++) {
        qa[ks][0] = __float_as_uint(KP[qr][(8 * ks + tg) ^ sx]);
        qa[ks][1] = __float_as_uint(KP[qr + 8][(8 * ks + tg) ^ sx]);
        qa[ks][2] = __float_as_uint(KP[qr][(8 * ks + tg + 4) ^ sx]);
        qa[ks][3] = __float_as_uint(KP[qr + 8][(8 * ks + tg + 4) ^ sx]);
    }

    float m0 = -1e30f, m1 = -1e30f, l0 = 0.f, l1 = 0.f;
    float4 od[8];
#pragma unroll
    for (int n = 0; n < 8; n++) od[n] = make_float4(0.f, 0.f, 0.f, 0.f);
    __syncthreads();   // Q gather done before K overwrites KP

    for (int k0 = 0; k0 < NT; k0 += 64) {
        // Load + convert K and V tiles
        {
            const float* kp_ = Kg + (size_t)(k0 + lr) * ND + lc0;
            const float* vp_ = Vg + (size_t)(k0 + lr) * ND + lc0;
#pragma unroll
            for (int j = 0; j < 8; j++) {
                float4 kv = *(const float4*)(kp_ + 4 * j);
                float4 ko = make_float4(f2tff(kv.x), f2tff(kv.y), f2tff(kv.z), f2tff(kv.w));
                *(float4*)&KP[lr][(lc0 + 4 * j) ^ (lr & 4)] = ko;
                float4 vv = *(const float4*)(vp_ + 4 * j);
                float4 vo = make_float4(f2tff(vv.x), f2tff(vv.y), f2tff(vv.z), f2tff(vv.w));
                *(float4*)&Vs[lr][(lc0 + 4 * j) ^ (lr & 4)] = vo;
            }
        }
        __syncthreads();

        // S = Q K^T  (warp: 16 q rows x 64 keys)
        float4 sv[8];
#pragma unroll
        for (int n = 0; n < 8; n++) sv[n] = make_float4(0.f, 0.f, 0.f, 0.f);
#pragma unroll
        for (int ks = 0; ks < 8; ks++) {
#pragma unroll
            for (int n = 0; n < 8; n++) {
                const int t = 8 * n + g;
                unsigned b0 = __float_as_uint(KP[t][(8 * ks + tg) ^ sx]);
                unsigned b1 = __float_as_uint(KP[t][(8 * ks + tg + 4) ^ sx]);
                mma8(sv[n], qa[ks][0], qa[ks][1], qa[ks][2], qa[ks][3], b0, b1);
            }
        }

        // Online softmax. Thread rows: qr (x,y regs) and qr+8 (z,w regs).
        float mx0 = -1e30f, mx1 = -1e30f;
#pragma unroll
        for (int n = 0; n < 8; n++) {
            sv[n].x *= 0.125f; sv[n].y *= 0.125f; sv[n].z *= 0.125f; sv[n].w *= 0.125f;
            mx0 = fmaxf(mx0, fmaxf(sv[n].x, sv[n].y));
            mx1 = fmaxf(mx1, fmaxf(sv[n].z, sv[n].w));
        }
        mx0 = fmaxf(mx0, __shfl_xor_sync(0xffffffffu, mx0, 1));
        mx0 = fmaxf(mx0, __shfl_xor_sync(0xffffffffu, mx0, 2));
        mx1 = fmaxf(mx1, __shfl_xor_sync(0xffffffffu, mx1, 1));
        mx1 = fmaxf(mx1, __shfl_xor_sync(0xffffffffu, mx1, 2));
        const float mn0 = fmaxf(m0, mx0), mn1 = fmaxf(m1, mx1);
        const float c0 = __expf(m0 - mn0), c1 = __expf(m1 - mn1);
        float s0 = 0.f, s1 = 0.f;
#pragma unroll
        for (int n = 0; n < 8; n++) {
            sv[n].x = __expf(sv[n].x - mn0); sv[n].y = __expf(sv[n].y - mn0);
            sv[n].z = __expf(sv[n].z - mn1); sv[n].w = __expf(sv[n].w - mn1);
            s0 += sv[n].x + sv[n].y;
            s1 += sv[n].z + sv[n].w;
        }
        s0 += __shfl_xor_sync(0xffffffffu, s0, 1);
        s0 += __shfl_xor_sync(0xffffffffu, s0, 2);
        s1 += __shfl_xor_sync(0xffffffffu, s1, 1);
        s1 += __shfl_xor_sync(0xffffffffu, s1, 2);
        l0 = l0 * c0 + s0; m0 = mn0;
        l1 = l1 * c1 + s1; m1 = mn1;
#pragma unroll
        for (int n = 0; n < 8; n++) {
            od[n].x *= c0; od[n].y *= c0; od[n].z *= c1; od[n].w *= c1;
        }
        __syncthreads();   // all warps done reading K from KP

        // Store P (tf32) into KP in C-fragment positions
#pragma unroll
        for (int n = 0; n < 8; n++) {
            const int cb = (8 * n + 2 * tg) ^ sx;   // XOR by 4 keeps float2 alignment
            *(float2*)&KP[qr][cb]     = make_float2(f2tff(sv[n].x), f2tff(sv[n].y));
            *(float2*)&KP[qr + 8][cb] = make_float2(f2tff(sv[n].z), f2tff(sv[n].w));
        }
        __syncthreads();

        // O += P @ V  (warp: 16 q rows x 64 d cols, k = 64 keys)
#pragma unroll
        for (int ks = 0; ks < 8; ks++) {
            unsigned pa0 = __float_as_uint(KP[qr][(8 * ks + tg) ^ sx]);
            unsigned pa1 = __float_as_uint(KP[qr + 8][(8 * ks + tg) ^ sx]);
            unsigned pa2 = __float_as_uint(KP[qr][(8 * ks + tg + 4) ^ sx]);
            unsigned pa3 = __float_as_uint(KP[qr + 8][(8 * ks + tg + 4) ^ sx]);
            const int kk = 8 * ks + tg;   // kk&4 == 0 (tg<4)
#pragma unroll
            for (int n = 0; n < 8; n++) {
                unsigned b0 = __float_as_uint(Vs[kk][8 * n + g]);
                unsigned b1 = __float_as_uint(Vs[kk + 4][(8 * n + g) ^ 4]);
                mma8(od[n], pa0, pa1, pa2, pa3, b0, b1);
            }
        }
        __syncthreads();   // before next tile overwrites KP/Vs
    }

    // Epilogue -> g_o [B,T,E]
    const int b = bh >> 4, h = bh & 15;
    const float i0 = 1.f / l0, i1 = 1.f / l1;
    const int t0 = q0 + qr, t1 = t0 + 8;
#pragma unroll
    for (int n = 0; n < 8; n++) {
        const int d = 8 * n + 2 * tg;
        *(float2*)&g_o[((size_t)(b * NT + t0)) * NE + h * 64 + d] =
            make_float2(od[n].x * i0, od[n].y * i0);
        *(float2*)&g_o[((size_t)(b * NT + t1)) * NE + h * 64 + d] =
            make_float2(od[n].z * i1, od[n].w * i1);
    }
}

// ---------------------------------------------------------------------------
extern "C" void kernel_launch(void* const* d_in, const int* in_sizes, int n_in,
                              void* d_out, int out_size) {
    const float* x     = (const float*)d_in[0];  // [2,2048,1024]
    const float* qkv_w = (const float*)d_in[1];  // [3072,1024]
    const float* qkv_b = (const float*)d_in[2];  // [3072]
    const float* out_w = (const float*)d_in[3];  // [1024,1024]
    const float* out_b = (const float*)d_in[4];  // [1024]
    float* out = (float*)d_out;                  // [2,2048,1024]

    dim3 g1(3 * NE / 64, NB * NT / 128);    // (48, 32)
    gemm_tf32<0><<<g1, 256>>>(x, qkv_w, qkv_b, nullptr);

    dim3 ga(NT / 64, NB * NH);              // (32, 32)
    attn_tf32<<<ga, 128>>>();

    dim3 g2(NE / 64, NB * NT / 128);        // (16, 32)
    gemm_tf32<1><<<g2, 256>>>(nullptr, out_w, out_b, out);
}